// round 2
// baseline (speedup 1.0000x reference)
#include <cuda_runtime.h>
#include <math.h>

// ---------------- problem dims (fixed by setup_inputs) ----------------
#define T_LEN   2048
#define BATCH   2
#define D_MODEL 1024
#define NHEAD   16
#define HD      64
#define VOCAB   5
#define BOT     800
#define SCALING 0.125f           // 64^-0.5
#define BD      (BATCH * D_MODEL)   // row stride in [T,B,D] tensors
#define ROWS    (T_LEN * BATCH)     // 4096 "rows" when flattened [T*B, D]

// ---------------- scratch (static device memory; no allocs) ----------------
__device__ __align__(256) float g_q[ROWS * D_MODEL];
__device__ __align__(256) float g_k[ROWS * D_MODEL];
__device__ __align__(256) float g_v[ROWS * D_MODEL];
__device__ __align__(256) float g_ctx[ROWS * D_MODEL];
__device__ __align__(256) float g_h[BATCH * BOT];
__device__ __align__(256) float g_pkv[BATCH * 2 * D_MODEL];

// ---------------- prefix MLP: h = tanh(W1[lang] @ emb + b1) ----------------
// grid (100, BATCH), 256 threads (8 warps). One warp per bottleneck output.
__global__ void prefix_h_kernel(const float* __restrict__ wte,
                                const float* __restrict__ w1,
                                const float* __restrict__ b1,
                                const int* __restrict__ lang) {
    int b    = blockIdx.y;
    int warp = threadIdx.x >> 5;
    int lane = threadIdx.x & 31;
    int j    = blockIdx.x * 8 + warp;          // 0..799
    if (j >= BOT) return;
    int L = lang[b];
    const float* e = wte + (size_t)L * D_MODEL;
    const float* w = w1 + ((size_t)L * BOT + j) * D_MODEL;
    float s = 0.f;
    for (int d = lane; d < D_MODEL; d += 32) s += e[d] * w[d];
    #pragma unroll
    for (int off = 16; off > 0; off >>= 1) s += __shfl_xor_sync(0xffffffffu, s, off);
    if (lane == 0) g_h[b * BOT + j] = tanhf(s + b1[(size_t)L * BOT + j]);
}

// ---------------- prefix MLP: kv = W2[lang] @ h + b2 ----------------
// grid (256, BATCH), 256 threads. One warp per output element of [2D].
__global__ void prefix_kv_kernel(const float* __restrict__ w2,
                                 const float* __restrict__ b2,
                                 const int* __restrict__ lang) {
    int b    = blockIdx.y;
    int warp = threadIdx.x >> 5;
    int lane = threadIdx.x & 31;
    int e    = blockIdx.x * 8 + warp;          // 0..2047
    int L = lang[b];
    const float* w = w2 + ((size_t)L * 2 * D_MODEL + e) * BOT;
    const float* h = g_h + b * BOT;
    float s = 0.f;
    for (int j = lane; j < BOT; j += 32) s += h[j] * w[j];
    #pragma unroll
    for (int off = 16; off > 0; off >>= 1) s += __shfl_xor_sync(0xffffffffu, s, off);
    if (lane == 0) g_pkv[b * 2 * D_MODEL + e] = s + b2[(size_t)L * 2 * D_MODEL + e];
}

// ---------------- tiled fp32 GEMM: C[m,n] = (sum_k A[m,k]*W[n,k] + bias[n]) * scale
// A:[M,K] row-major, W:[N,K] row-major. 64x64 tile, BK=32, 256 thr, 4x4 micro.
__global__ void gemm_bias_kernel(const float* __restrict__ A,
                                 const float* __restrict__ W,
                                 const float* __restrict__ bias,
                                 float* __restrict__ C,
                                 int M, int N, int K, float scale) {
    __shared__ float As[32 * 68];   // As[k*68 + m]
    __shared__ float Bs[32 * 68];   // Bs[k*68 + n]
    int tid = threadIdx.x;
    int tx = tid & 15, ty = tid >> 4;
    int m0 = blockIdx.y * 64, n0 = blockIdx.x * 64;

    float acc[4][4];
    #pragma unroll
    for (int i = 0; i < 4; i++)
        #pragma unroll
        for (int j = 0; j < 4; j++) acc[i][j] = 0.f;

    for (int k0 = 0; k0 < K; k0 += 32) {
        __syncthreads();
        #pragma unroll
        for (int p = tid; p < 64 * 32; p += 256) {
            int k = p & 31, r = p >> 5;
            As[k * 68 + r] = A[(size_t)(m0 + r) * K + k0 + k];
            Bs[k * 68 + r] = W[(size_t)(n0 + r) * K + k0 + k];
        }
        __syncthreads();
        #pragma unroll 8
        for (int k = 0; k < 32; k++) {
            float4 a = *(const float4*)(As + k * 68 + ty * 4);
            float4 bb = *(const float4*)(Bs + k * 68 + tx * 4);
            float av[4] = {a.x, a.y, a.z, a.w};
            float bv[4] = {bb.x, bb.y, bb.z, bb.w};
            #pragma unroll
            for (int i = 0; i < 4; i++)
                #pragma unroll
                for (int j = 0; j < 4; j++) acc[i][j] += av[i] * bv[j];
        }
    }

    float bj[4];
    #pragma unroll
    for (int j = 0; j < 4; j++) bj[j] = bias[n0 + tx * 4 + j];
    #pragma unroll
    for (int i = 0; i < 4; i++) {
        int row = m0 + ty * 4 + i;
        float4 out;
        out.x = (acc[i][0] + bj[0]) * scale;
        out.y = (acc[i][1] + bj[1]) * scale;
        out.z = (acc[i][2] + bj[2]) * scale;
        out.w = (acc[i][3] + bj[3]) * scale;
        *(float4*)(C + (size_t)row * N + n0 + tx * 4) = out;
    }
}

// ---------------- flash attention with 1 prefix token ----------------
// grid (T/64, H, B), 256 threads. Q/K transposed in smem; P reuses K buffer.
// smem: Qs[d*64+q] (4096) | Ks[d*68+k] (4352, reused as Ps[k*65+q]) | Vs[k*64+d] (4096)
#define SM_Q 0
#define SM_K 4096
#define SM_V (4096 + 4352)
#define SMEM_FLOATS (4096 + 4352 + 4096)

__global__ void attn_kernel(void) {
    extern __shared__ float sm[];
    float* Qs = sm + SM_Q;
    float* Ks = sm + SM_K;
    float* Vs = sm + SM_V;

    int b = blockIdx.z, h = blockIdx.y;
    int t0 = blockIdx.x * 64;
    int tid = threadIdx.x;
    int tx = tid & 15, ty = tid >> 4;

    const float* qbase = g_q + (size_t)t0 * BD + b * D_MODEL + h * HD;
    const float* kbase = g_k + (size_t)b * D_MODEL + h * HD;
    const float* vbase = g_v + (size_t)b * D_MODEL + h * HD;

    // load Q tile transposed: Qs[d][qi]
    #pragma unroll
    for (int p = tid; p < 64 * 64; p += 256) {
        int d = p & 63, qi = p >> 6;
        Qs[d * 64 + qi] = qbase[(size_t)qi * BD + d];
    }
    __syncthreads();

    // prefix token init
    const float* pk = g_pkv + b * 2 * D_MODEL + h * HD;
    const float* pv = pk + D_MODEL;
    float m[4], l[4], O[4][4];
    {
        float part[4] = {0.f, 0.f, 0.f, 0.f};
        #pragma unroll
        for (int dd = 0; dd < 4; dd++) {
            float kv = pk[tx * 4 + dd];
            #pragma unroll
            for (int i = 0; i < 4; i++)
                part[i] += Qs[(tx * 4 + dd) * 64 + ty * 4 + i] * kv;
        }
        #pragma unroll
        for (int off = 8; off > 0; off >>= 1)
            #pragma unroll
            for (int i = 0; i < 4; i++)
                part[i] += __shfl_xor_sync(0xffffffffu, part[i], off);
        #pragma unroll
        for (int i = 0; i < 4; i++) { m[i] = part[i]; l[i] = 1.0f; }
        #pragma unroll
        for (int j = 0; j < 4; j++) {
            float pvv = pv[tx * 4 + j];
            #pragma unroll
            for (int i = 0; i < 4; i++) O[i][j] = pvv;
        }
    }

    for (int kt = 0; kt < T_LEN / 64; kt++) {
        __syncthreads();   // protect Ks/Vs from previous iteration's readers
        #pragma unroll
        for (int p = tid; p < 64 * 64; p += 256) {
            int d = p & 63, ki = p >> 6;
            size_t g = (size_t)(kt * 64 + ki) * BD + d;
            Ks[d * 68 + ki] = kbase[g];
            Vs[ki * 64 + d] = vbase[g];
        }
        __syncthreads();

        // S = Q @ K^T   (q already scaled)
        float s[4][4];
        #pragma unroll
        for (int i = 0; i < 4; i++)
            #pragma unroll
            for (int j = 0; j < 4; j++) s[i][j] = 0.f;
        #pragma unroll 8
        for (int d = 0; d < 64; d++) {
            float4 a = *(const float4*)(Qs + d * 64 + ty * 4);
            float4 bb = *(const float4*)(Ks + d * 68 + tx * 4);
            float av[4] = {a.x, a.y, a.z, a.w};
            float bv[4] = {bb.x, bb.y, bb.z, bb.w};
            #pragma unroll
            for (int i = 0; i < 4; i++)
                #pragma unroll
                for (int j = 0; j < 4; j++) s[i][j] += av[i] * bv[j];
        }

        // online softmax update
        float rm[4], rs[4];
        #pragma unroll
        for (int i = 0; i < 4; i++) {
            rm[i] = fmaxf(fmaxf(s[i][0], s[i][1]), fmaxf(s[i][2], s[i][3]));
        }
        #pragma unroll
        for (int off = 8; off > 0; off >>= 1)
            #pragma unroll
            for (int i = 0; i < 4; i++)
                rm[i] = fmaxf(rm[i], __shfl_xor_sync(0xffffffffu, rm[i], off));
        float f[4];
        #pragma unroll
        for (int i = 0; i < 4; i++) {
            float mn = fmaxf(m[i], rm[i]);
            f[i] = __expf(m[i] - mn);
            m[i] = mn;
            rs[i] = 0.f;
            #pragma unroll
            for (int j = 0; j < 4; j++) {
                s[i][j] = __expf(s[i][j] - mn);
                rs[i] += s[i][j];
            }
        }
        #pragma unroll
        for (int off = 8; off > 0; off >>= 1)
            #pragma unroll
            for (int i = 0; i < 4; i++)
                rs[i] += __shfl_xor_sync(0xffffffffu, rs[i], off);
        #pragma unroll
        for (int i = 0; i < 4; i++) {
            l[i] = l[i] * f[i] + rs[i];
            #pragma unroll
            for (int j = 0; j < 4; j++) O[i][j] *= f[i];
        }

        __syncthreads();   // all lanes done reading Ks
        // write P into the freed K buffer: Ps[k*65 + q]
        #pragma unroll
        for (int j = 0; j < 4; j++)
            #pragma unroll
            for (int i = 0; i < 4; i++)
                Ks[(tx * 4 + j) * 65 + ty * 4 + i] = s[i][j];
        __syncthreads();

        // O += P @ V
        #pragma unroll 8
        for (int k2 = 0; k2 < 64; k2++) {
            float a0 = Ks[k2 * 65 + ty * 4 + 0];
            float a1 = Ks[k2 * 65 + ty * 4 + 1];
            float a2 = Ks[k2 * 65 + ty * 4 + 2];
            float a3 = Ks[k2 * 65 + ty * 4 + 3];
            float4 bb = *(const float4*)(Vs + k2 * 64 + tx * 4);
            float bv[4] = {bb.x, bb.y, bb.z, bb.w};
            #pragma unroll
            for (int j = 0; j < 4; j++) {
                O[0][j] += a0 * bv[j];
                O[1][j] += a1 * bv[j];
                O[2][j] += a2 * bv[j];
                O[3][j] += a3 * bv[j];
            }
        }
    }

    // epilogue: normalize and write ctx in [T,B,D] layout
    #pragma unroll
    for (int i = 0; i < 4; i++) {
        float inv = 1.0f / l[i];
        int t = t0 + ty * 4 + i;
        float4 out;
        out.x = O[i][0] * inv;
        out.y = O[i][1] * inv;
        out.z = O[i][2] * inv;
        out.w = O[i][3] * inv;
        *(float4*)(g_ctx + (size_t)t * BD + b * D_MODEL + h * HD + tx * 4) = out;
    }
}

// ---------------- launch ----------------
extern "C" void kernel_launch(void* const* d_in, const int* in_sizes, int n_in,
                              void* d_out, int out_size) {
    const float* query = (const float*)d_in[0];
    const float* key   = (const float*)d_in[1];
    const float* value = (const float*)d_in[2];
    const float* wq    = (const float*)d_in[3];
    const float* bq    = (const float*)d_in[4];
    const float* wk    = (const float*)d_in[5];
    const float* bk    = (const float*)d_in[6];
    const float* wv    = (const float*)d_in[7];
    const float* bv    = (const float*)d_in[8];
    const float* wo    = (const float*)d_in[9];
    const float* bo    = (const float*)d_in[10];
    const float* wte   = (const float*)d_in[11];
    const float* ct_w1 = (const float*)d_in[12];
    const float* ct_b1 = (const float*)d_in[13];
    const float* ct_w2 = (const float*)d_in[14];
    const float* ct_b2 = (const float*)d_in[15];
    const int*   lang  = (const int*)d_in[16];
    float* out = (float*)d_out;

    (void)in_sizes; (void)n_in; (void)out_size;

    // prefix KV (tiny)
    prefix_h_kernel<<<dim3(100, BATCH), 256>>>(wte, ct_w1, ct_b1, lang);
    prefix_kv_kernel<<<dim3(256, BATCH), 256>>>(ct_w2, ct_b2, lang);

    // projections
    float* dq; cudaGetSymbolAddress((void**)&dq, g_q);
    float* dk; cudaGetSymbolAddress((void**)&dk, g_k);
    float* dv; cudaGetSymbolAddress((void**)&dv, g_v);
    float* dctx; cudaGetSymbolAddress((void**)&dctx, g_ctx);

    dim3 ggrid(D_MODEL / 64, ROWS / 64);   // (16, 64)
    gemm_bias_kernel<<<ggrid, 256>>>(query, wq, bq, dq, ROWS, D_MODEL, D_MODEL, SCALING);
    gemm_bias_kernel<<<ggrid, 256>>>(key,   wk, bk, dk, ROWS, D_MODEL, D_MODEL, 1.0f);
    gemm_bias_kernel<<<ggrid, 256>>>(value, wv, bv, dv, ROWS, D_MODEL, D_MODEL, 1.0f);

    // attention
    size_t smem_bytes = SMEM_FLOATS * sizeof(float);
    cudaFuncSetAttribute(attn_kernel, cudaFuncAttributeMaxDynamicSharedMemorySize,
                         (int)smem_bytes);
    attn_kernel<<<dim3(T_LEN / 64, NHEAD, BATCH), 256, smem_bytes>>>();

    // output projection
    gemm_bias_kernel<<<ggrid, 256>>>(dctx, wo, bo, out, ROWS, D_MODEL, D_MODEL, 1.0f);
}

// round 9
// speedup vs baseline: 2.5564x; 2.5564x over previous
#include <cuda_runtime.h>
#include <cuda_bf16.h>
#include <math.h>
#include <stdint.h>

// ---------------- problem dims (fixed by setup_inputs) ----------------
#define T_LEN   2048
#define BATCH   2
#define D_MODEL 1024
#define NHEAD   16
#define HD      64
#define VOCAB   5
#define BOT     800
#define SCALING 0.125f
#define BD      (BATCH * D_MODEL)
#define ROWS    (T_LEN * BATCH)      // 4096

// ---------------- scratch (static device memory; no allocs) ----------------
__device__ __align__(256) float g_q[ROWS * D_MODEL];
__device__ __align__(256) float g_k[ROWS * D_MODEL];
__device__ __align__(256) float g_v[ROWS * D_MODEL];
__device__ __align__(256) float g_ctx[ROWS * D_MODEL];
__device__ __align__(256) float g_h[BATCH * BOT];
__device__ __align__(256) float g_pkv[BATCH * 2 * D_MODEL];

// ================= helpers =================
__device__ __forceinline__ uint32_t smem_to_u32(const void* p) {
    uint32_t a;
    asm("{ .reg .u64 t; cvta.to.shared.u64 t, %1; cvt.u32.u64 %0, t; }" : "=r"(a) : "l"(p));
    return a;
}

__device__ __forceinline__ void ldsm_x4(uint32_t* r, uint32_t addr) {
    asm volatile("ldmatrix.sync.aligned.m8n8.x4.shared.b16 {%0,%1,%2,%3}, [%4];"
        : "=r"(r[0]), "=r"(r[1]), "=r"(r[2]), "=r"(r[3]) : "r"(addr));
}
__device__ __forceinline__ void ldsm_x2(uint32_t* r, uint32_t addr) {
    asm volatile("ldmatrix.sync.aligned.m8n8.x2.shared.b16 {%0,%1}, [%2];"
        : "=r"(r[0]), "=r"(r[1]) : "r"(addr));
}
__device__ __forceinline__ void ldsm_x2_trans(uint32_t* r, uint32_t addr) {
    asm volatile("ldmatrix.sync.aligned.m8n8.x2.trans.shared.b16 {%0,%1}, [%2];"
        : "=r"(r[0]), "=r"(r[1]) : "r"(addr));
}
// D += A*B, m16n8k16 bf16 -> fp32
__device__ __forceinline__ void mma_bf16(float* d, const uint32_t* a, const uint32_t* b) {
    asm volatile("mma.sync.aligned.m16n8k16.row.col.f32.bf16.bf16.f32 "
        "{%0,%1,%2,%3}, {%4,%5,%6,%7}, {%8,%9}, {%0,%1,%2,%3};"
        : "+f"(d[0]), "+f"(d[1]), "+f"(d[2]), "+f"(d[3])
        : "r"(a[0]), "r"(a[1]), "r"(a[2]), "r"(a[3]), "r"(b[0]), "r"(b[1]));
}

// split two fp32 into packed bf16x2 (hi) and bf16x2 (residual lo)
__device__ __forceinline__ void split2(float x, float y, uint32_t& hi, uint32_t& lo) {
    __nv_bfloat16 hx = __float2bfloat16_rn(x), hy = __float2bfloat16_rn(y);
    __nv_bfloat16 lx = __float2bfloat16_rn(x - __bfloat162float(hx));
    __nv_bfloat16 ly = __float2bfloat16_rn(y - __bfloat162float(hy));
    __nv_bfloat162 h = __halves2bfloat162(hx, hy);
    __nv_bfloat162 l = __halves2bfloat162(lx, ly);
    hi = *(uint32_t*)&h;
    lo = *(uint32_t*)&l;
}

// ---------------- prefix MLP kernels (tiny) ----------------
__global__ void prefix_h_kernel(const float* __restrict__ wte,
                                const float* __restrict__ w1,
                                const float* __restrict__ b1,
                                const int* __restrict__ lang) {
    int b = blockIdx.y, warp = threadIdx.x >> 5, lane = threadIdx.x & 31;
    int j = blockIdx.x * 8 + warp;
    if (j >= BOT) return;
    int L = lang[b];
    const float* e = wte + (size_t)L * D_MODEL;
    const float* w = w1 + ((size_t)L * BOT + j) * D_MODEL;
    float s = 0.f;
    for (int d = lane; d < D_MODEL; d += 32) s += e[d] * w[d];
    #pragma unroll
    for (int off = 16; off > 0; off >>= 1) s += __shfl_xor_sync(0xffffffffu, s, off);
    if (lane == 0) g_h[b * BOT + j] = tanhf(s + b1[(size_t)L * BOT + j]);
}

__global__ void prefix_kv_kernel(const float* __restrict__ w2,
                                 const float* __restrict__ b2,
                                 const int* __restrict__ lang) {
    int b = blockIdx.y, warp = threadIdx.x >> 5, lane = threadIdx.x & 31;
    int e = blockIdx.x * 8 + warp;
    int L = lang[b];
    const float* w = w2 + ((size_t)L * 2 * D_MODEL + e) * BOT;
    const float* h = g_h + b * BOT;
    float s = 0.f;
    for (int j = lane; j < BOT; j += 32) s += h[j] * w[j];
    #pragma unroll
    for (int off = 16; off > 0; off >>= 1) s += __shfl_xor_sync(0xffffffffu, s, off);
    if (lane == 0) g_pkv[b * 2 * D_MODEL + e] = s + b2[(size_t)L * 2 * D_MODEL + e];
}

// ================= mma.sync split-bf16 projection GEMM =================
// C[m,n] = (sum_k A[m,k]*W[n,k] + bias[n]) * scale
// Tile: 128x128, BK=32, 256 thr / 8 warps (2x4), warp tile 64x32.
#define BM 128
#define BN 128
#define BK 32
#define KSTR 40
#define SM_AHI 0
#define SM_ALO (128 * KSTR)
#define SM_BHI (2 * 128 * KSTR)
#define SM_BLO (3 * 128 * KSTR)
#define GEMM_SMEM_HALVES (4 * 128 * KSTR)

__global__ void __launch_bounds__(256, 1)
gemm_mma_kernel(const float* __restrict__ A, const float* __restrict__ W,
                const float* __restrict__ bias, float* __restrict__ C, float scale) {
    __shared__ __nv_bfloat16 sh[GEMM_SMEM_HALVES];
    uint32_t shu = smem_to_u32(sh);
    int tid = threadIdx.x, lane = tid & 31, wid = tid >> 5;
    int m0 = blockIdx.y * BM, n0 = blockIdx.x * BN;
    int mw = (wid & 1) * 64, nw = (wid >> 1) * 32;

    float acc[4][4][4];
    #pragma unroll
    for (int i = 0; i < 4; i++)
        #pragma unroll
        for (int j = 0; j < 4; j++)
            #pragma unroll
            for (int c = 0; c < 4; c++) acc[i][j][c] = 0.f;

    for (int k0 = 0; k0 < D_MODEL; k0 += BK) {
        float4 ra[4], rw[4];
        #pragma unroll
        for (int i = 0; i < 4; i++) {
            int idx = tid + i * 256;
            int r = idx >> 3, kc = (idx & 7) * 4;
            ra[i] = *(const float4*)(A + (size_t)(m0 + r) * D_MODEL + k0 + kc);
            rw[i] = *(const float4*)(W + (size_t)(n0 + r) * D_MODEL + k0 + kc);
        }
        __syncthreads();
        #pragma unroll
        for (int i = 0; i < 4; i++) {
            int idx = tid + i * 256;
            int r = idx >> 3, kc = (idx & 7) * 4;
            uint32_t h0, l0, h1, l1;
            split2(ra[i].x, ra[i].y, h0, l0);
            split2(ra[i].z, ra[i].w, h1, l1);
            *(uint2*)(sh + SM_AHI + r * KSTR + kc) = make_uint2(h0, h1);
            *(uint2*)(sh + SM_ALO + r * KSTR + kc) = make_uint2(l0, l1);
            split2(rw[i].x, rw[i].y, h0, l0);
            split2(rw[i].z, rw[i].w, h1, l1);
            *(uint2*)(sh + SM_BHI + r * KSTR + kc) = make_uint2(h0, h1);
            *(uint2*)(sh + SM_BLO + r * KSTR + kc) = make_uint2(l0, l1);
        }
        __syncthreads();

        #pragma unroll
        for (int ks = 0; ks < BK; ks += 16) {
            uint32_t ahi[4][4], alo[4][4], bhi[4][2], blo[4][2];
            int arow = mw + (lane & 15);
            int acol = ks + (lane >> 4) * 8;
            #pragma unroll
            for (int mt = 0; mt < 4; mt++) {
                uint32_t off = (uint32_t)(((arow + mt * 16) * KSTR + acol) * 2);
                ldsm_x4(ahi[mt], shu + SM_AHI * 2 + off);
                ldsm_x4(alo[mt], shu + SM_ALO * 2 + off);
            }
            int brow = nw + (lane & 7);
            int bcol = ks + ((lane >> 3) & 1) * 8;
            #pragma unroll
            for (int nt = 0; nt < 4; nt++) {
                uint32_t off = (uint32_t)(((brow + nt * 8) * KSTR + bcol) * 2);
                ldsm_x2(bhi[nt], shu + SM_BHI * 2 + off);
                ldsm_x2(blo[nt], shu + SM_BLO * 2 + off);
            }
            #pragma unroll
            for (int mt = 0; mt < 4; mt++)
                #pragma unroll
                for (int nt = 0; nt < 4; nt++) {
                    mma_bf16(acc[mt][nt], ahi[mt], bhi[nt]);
                    mma_bf16(acc[mt][nt], ahi[mt], blo[nt]);
                    mma_bf16(acc[mt][nt], alo[mt], bhi[nt]);
                }
        }
    }

    #pragma unroll
    for (int mt = 0; mt < 4; mt++) {
        int r0 = m0 + mw + mt * 16 + (lane >> 2);
        #pragma unroll
        for (int nt = 0; nt < 4; nt++) {
            int c = n0 + nw + nt * 8 + (lane & 3) * 2;
            float2 bb = *(const float2*)(bias + c);
            float2 o0, o1;
            o0.x = (acc[mt][nt][0] + bb.x) * scale;
            o0.y = (acc[mt][nt][1] + bb.y) * scale;
            o1.x = (acc[mt][nt][2] + bb.x) * scale;
            o1.y = (acc[mt][nt][3] + bb.y) * scale;
            *(float2*)(C + (size_t)r0 * D_MODEL + c) = o0;
            *(float2*)(C + (size_t)(r0 + 8) * D_MODEL + c) = o1;
        }
    }
}

// ================= mma.sync flash attention (split-bf16) =================
// CTA: 128 query rows, 8 warps (warp = m16). K-tiles of 64 keys.
// S = Qhi*Khi + Qhi*Klo + Qlo*Khi ; O += Phi*Vhi + Phi*Vlo + Plo*Vhi.
// K,V stored [key][hd] stride A_STR; V B-frags via ldmatrix.trans.
#define A_STR 72
#define AQHI 0
#define AQLO (128 * A_STR)                  // 9216
#define AKHI (2 * 128 * A_STR)              // 18432
#define AKLO (AKHI + 64 * A_STR)            // 23040
#define AVHI (AKLO + 64 * A_STR)            // 27648
#define AVLO (AVHI + 64 * A_STR)            // 32256
#define ATT_SMEM_HALVES (AVLO + 64 * A_STR) // 36864 halves = 73728 B

__global__ void __launch_bounds__(256, 1)
attn_mma_kernel(void) {
    extern __shared__ __nv_bfloat16 ash[];
    uint32_t shu = smem_to_u32(ash);
    int b = blockIdx.z, h = blockIdx.y;
    int t0 = blockIdx.x * 128;
    int tid = threadIdx.x, lane = tid & 31, wid = tid >> 5;

    const float* qbase = g_q + (size_t)t0 * BD + b * D_MODEL + h * HD;
    const float* kbase = g_k + (size_t)b * D_MODEL + h * HD;
    const float* vbase = g_v + (size_t)b * D_MODEL + h * HD;

    // ---- load Q tile (128x64) split into smem ----
    {
        int row = tid >> 1, c0 = (tid & 1) * 32;
        const float* qp = qbase + (size_t)row * BD + c0;
        #pragma unroll
        for (int i = 0; i < 8; i++) {
            float4 f = *(const float4*)(qp + i * 4);
            uint32_t h0, l0, h1, l1;
            split2(f.x, f.y, h0, l0);
            split2(f.z, f.w, h1, l1);
            int off = row * A_STR + c0 + i * 4;
            *(uint32_t*)(ash + AQHI + off) = h0;
            *(uint32_t*)(ash + AQHI + off + 2) = h1;
            *(uint32_t*)(ash + AQLO + off) = l0;
            *(uint32_t*)(ash + AQLO + off + 2) = l1;
        }
    }

    // ---- prefix token: init m with prefix score, O with pv, l = 1 ----
    const float* pk = g_pkv + b * 2 * D_MODEL + h * HD;
    const float* pv = pk + D_MODEL;
    int r0 = wid * 16 + (lane >> 2);   // CTA-local query row for acc c0,c1
    int r1 = r0 + 8;                   // for acc c2,c3
    float m0, m1, l0 = 1.f, l1 = 1.f;
    {
        float s0 = 0.f, s1 = 0.f;
        const float* q0 = qbase + (size_t)r0 * BD;
        const float* q1 = qbase + (size_t)r1 * BD;
        #pragma unroll 8
        for (int d = 0; d < HD; d++) {
            float kv = pk[d];
            s0 += q0[d] * kv;
            s1 += q1[d] * kv;
        }
        m0 = s0; m1 = s1;
    }
    float O[8][4];
    #pragma unroll
    for (int nt = 0; nt < 8; nt++) {
        int c = nt * 8 + (lane & 3) * 2;
        O[nt][0] = pv[c];     O[nt][1] = pv[c + 1];
        O[nt][2] = pv[c];     O[nt][3] = pv[c + 1];
    }

    // ---- mainloop over 32 K-tiles of 64 keys ----
    for (int kt = 0; kt < T_LEN / 64; kt++) {
        __syncthreads();   // previous tile's readers done (also orders Q writes at kt=0)
        // K tile load (64x64), split
        {
            int key = tid >> 2, c0 = (tid & 3) * 16;
            const float* kp = kbase + (size_t)(kt * 64 + key) * BD + c0;
            #pragma unroll
            for (int i = 0; i < 4; i++) {
                float4 f = *(const float4*)(kp + i * 4);
                uint32_t h0, l0r, h1, l1r;
                split2(f.x, f.y, h0, l0r);
                split2(f.z, f.w, h1, l1r);
                int off = key * A_STR + c0 + i * 4;
                *(uint32_t*)(ash + AKHI + off) = h0;
                *(uint32_t*)(ash + AKHI + off + 2) = h1;
                *(uint32_t*)(ash + AKLO + off) = l0r;
                *(uint32_t*)(ash + AKLO + off + 2) = l1r;
            }
        }
        // V tile load (64x64), split, same layout (trans happens at ldmatrix)
        {
            int key = tid >> 2, c0 = (tid & 3) * 16;
            const float* vp = vbase + (size_t)(kt * 64 + key) * BD + c0;
            #pragma unroll
            for (int i = 0; i < 4; i++) {
                float4 f = *(const float4*)(vp + i * 4);
                uint32_t h0, l0r, h1, l1r;
                split2(f.x, f.y, h0, l0r);
                split2(f.z, f.w, h1, l1r);
                int off = key * A_STR + c0 + i * 4;
                *(uint32_t*)(ash + AVHI + off) = h0;
                *(uint32_t*)(ash + AVHI + off + 2) = h1;
                *(uint32_t*)(ash + AVLO + off) = l0r;
                *(uint32_t*)(ash + AVLO + off + 2) = l1r;
            }
        }
        __syncthreads();

        // ---- S = Q @ K^T (split, fp32 acc); warp computes m16 x n64 ----
        float s[8][4];
        #pragma unroll
        for (int nt = 0; nt < 8; nt++)
            #pragma unroll
            for (int c = 0; c < 4; c++) s[nt][c] = 0.f;

        #pragma unroll
        for (int ks = 0; ks < 4; ks++) {
            uint32_t ahi[4], alo[4];
            int ar = wid * 16 + (lane & 15);
            int ac = ks * 16 + (lane >> 4) * 8;
            uint32_t aoff = (uint32_t)((ar * A_STR + ac) * 2);
            ldsm_x4(ahi, shu + AQHI * 2 + aoff);
            ldsm_x4(alo, shu + AQLO * 2 + aoff);
            #pragma unroll
            for (int nt = 0; nt < 8; nt++) {
                int br = nt * 8 + (lane & 7);
                int bc = ks * 16 + ((lane >> 3) & 1) * 8;
                uint32_t boff = (uint32_t)((br * A_STR + bc) * 2);
                uint32_t bhi[2], blo[2];
                ldsm_x2(bhi, shu + AKHI * 2 + boff);
                ldsm_x2(blo, shu + AKLO * 2 + boff);
                mma_bf16(s[nt], ahi, bhi);
                mma_bf16(s[nt], ahi, blo);
                mma_bf16(s[nt], alo, bhi);
            }
        }

        // ---- online softmax (rows r0, r1; quad = lanes sharing a row) ----
        float mx0 = s[0][0], mx1 = s[0][2];
        #pragma unroll
        for (int nt = 0; nt < 8; nt++) {
            mx0 = fmaxf(mx0, fmaxf(s[nt][0], s[nt][1]));
            mx1 = fmaxf(mx1, fmaxf(s[nt][2], s[nt][3]));
        }
        mx0 = fmaxf(mx0, __shfl_xor_sync(0xffffffffu, mx0, 1));
        mx0 = fmaxf(mx0, __shfl_xor_sync(0xffffffffu, mx0, 2));
        mx1 = fmaxf(mx1, __shfl_xor_sync(0xffffffffu, mx1, 1));
        mx1 = fmaxf(mx1, __shfl_xor_sync(0xffffffffu, mx1, 2));
        float mn0 = fmaxf(m0, mx0), mn1 = fmaxf(m1, mx1);
        float f0 = __expf(m0 - mn0), f1 = __expf(m1 - mn1);
        m0 = mn0; m1 = mn1;
        float sum0 = 0.f, sum1 = 0.f;
        #pragma unroll
        for (int nt = 0; nt < 8; nt++) {
            s[nt][0] = __expf(s[nt][0] - mn0);
            s[nt][1] = __expf(s[nt][1] - mn0);
            s[nt][2] = __expf(s[nt][2] - mn1);
            s[nt][3] = __expf(s[nt][3] - mn1);
            sum0 += s[nt][0] + s[nt][1];
            sum1 += s[nt][2] + s[nt][3];
        }
        sum0 += __shfl_xor_sync(0xffffffffu, sum0, 1);
        sum0 += __shfl_xor_sync(0xffffffffu, sum0, 2);
        sum1 += __shfl_xor_sync(0xffffffffu, sum1, 1);
        sum1 += __shfl_xor_sync(0xffffffffu, sum1, 2);
        l0 = l0 * f0 + sum0;
        l1 = l1 * f1 + sum1;
        #pragma unroll
        for (int nt = 0; nt < 8; nt++) {
            O[nt][0] *= f0; O[nt][1] *= f0;
            O[nt][2] *= f1; O[nt][3] *= f1;
        }

        // ---- O += P @ V (split); P A-frags re-packed from S accs ----
        #pragma unroll
        for (int kc = 0; kc < 4; kc++) {
            uint32_t phi[4], plo[4];
            split2(s[2 * kc][0],     s[2 * kc][1],     phi[0], plo[0]);
            split2(s[2 * kc][2],     s[2 * kc][3],     phi[1], plo[1]);
            split2(s[2 * kc + 1][0], s[2 * kc + 1][1], phi[2], plo[2]);
            split2(s[2 * kc + 1][2], s[2 * kc + 1][3], phi[3], plo[3]);
            #pragma unroll
            for (int nt = 0; nt < 8; nt++) {
                int vr = kc * 16 + (lane & 15);      // key row
                uint32_t boff = (uint32_t)((vr * A_STR + nt * 8) * 2);
                uint32_t bhi[2], blo[2];
                ldsm_x2_trans(bhi, shu + AVHI * 2 + boff);
                ldsm_x2_trans(blo, shu + AVLO * 2 + boff);
                mma_bf16(O[nt], phi, bhi);
                mma_bf16(O[nt], phi, blo);
                mma_bf16(O[nt], plo, bhi);
            }
        }
    }

    // ---- epilogue ----
    float inv0 = 1.0f / l0, inv1 = 1.0f / l1;
    #pragma unroll
    for (int nt = 0; nt < 8; nt++) {
        int c = h * HD + nt * 8 + (lane & 3) * 2;
        float2 o0, o1;
        o0.x = O[nt][0] * inv0; o0.y = O[nt][1] * inv0;
        o1.x = O[nt][2] * inv1; o1.y = O[nt][3] * inv1;
        *(float2*)(g_ctx + (size_t)(t0 + r0) * BD + b * D_MODEL + c) = o0;
        *(float2*)(g_ctx + (size_t)(t0 + r1) * BD + b * D_MODEL + c) = o1;
    }
}

// ---------------- launch ----------------
extern "C" void kernel_launch(void* const* d_in, const int* in_sizes, int n_in,
                              void* d_out, int out_size) {
    const float* query = (const float*)d_in[0];
    const float* key   = (const float*)d_in[1];
    const float* value = (const float*)d_in[2];
    const float* wq    = (const float*)d_in[3];
    const float* bq    = (const float*)d_in[4];
    const float* wk    = (const float*)d_in[5];
    const float* bk    = (const float*)d_in[6];
    const float* wv    = (const float*)d_in[7];
    const float* bv    = (const float*)d_in[8];
    const float* wo    = (const float*)d_in[9];
    const float* bo    = (const float*)d_in[10];
    const float* wte   = (const float*)d_in[11];
    const float* ct_w1 = (const float*)d_in[12];
    const float* ct_b1 = (const float*)d_in[13];
    const float* ct_w2 = (const float*)d_in[14];
    const float* ct_b2 = (const float*)d_in[15];
    const int*   lang  = (const int*)d_in[16];
    float* out = (float*)d_out;

    (void)in_sizes; (void)n_in; (void)out_size;

    prefix_h_kernel<<<dim3(100, BATCH), 256>>>(wte, ct_w1, ct_b1, lang);
    prefix_kv_kernel<<<dim3(256, BATCH), 256>>>(ct_w2, ct_b2, lang);

    float* dq; cudaGetSymbolAddress((void**)&dq, g_q);
    float* dk; cudaGetSymbolAddress((void**)&dk, g_k);
    float* dv; cudaGetSymbolAddress((void**)&dv, g_v);
    float* dctx; cudaGetSymbolAddress((void**)&dctx, g_ctx);

    dim3 ggrid(D_MODEL / BN, ROWS / BM);   // (8, 32)
    gemm_mma_kernel<<<ggrid, 256>>>(query, wq, bq, dq, SCALING);
    gemm_mma_kernel<<<ggrid, 256>>>(key,   wk, bk, dk, 1.0f);
    gemm_mma_kernel<<<ggrid, 256>>>(value, wv, bv, dv, 1.0f);

    size_t att_smem = ATT_SMEM_HALVES * sizeof(__nv_bfloat16);   // 73728 B
    cudaFuncSetAttribute(attn_mma_kernel, cudaFuncAttributeMaxDynamicSharedMemorySize,
                         (int)att_smem);
    attn_mma_kernel<<<dim3(T_LEN / 128, NHEAD, BATCH), 256, att_smem>>>();

    gemm_mma_kernel<<<ggrid, 256>>>(dctx, wo, bo, out, 1.0f);
}

// round 11
// speedup vs baseline: 2.9954x; 1.1717x over previous
#include <cuda_runtime.h>
#include <cuda_bf16.h>
#include <math.h>
#include <stdint.h>

// ---------------- problem dims (fixed by setup_inputs) ----------------
#define T_LEN   2048
#define BATCH   2
#define D_MODEL 1024
#define NHEAD   16
#define HD      64
#define VOCAB   5
#define BOT     800
#define SCALING 0.125f
#define BD      (BATCH * D_MODEL)
#define ROWS    (T_LEN * BATCH)      // 4096

// ---------------- scratch (static device memory; no allocs) ----------------
__device__ __align__(256) float g_q[ROWS * D_MODEL];
__device__ __align__(256) float g_k[ROWS * D_MODEL];
__device__ __align__(256) float g_v[ROWS * D_MODEL];
__device__ __align__(256) float g_ctx[ROWS * D_MODEL];
__device__ __align__(256) float g_h[BATCH * BOT];
__device__ __align__(256) float g_pkv[BATCH * 2 * D_MODEL];

// ================= helpers =================
__device__ __forceinline__ uint32_t smem_to_u32(const void* p) {
    uint32_t a;
    asm("{ .reg .u64 t; cvta.to.shared.u64 t, %1; cvt.u32.u64 %0, t; }" : "=r"(a) : "l"(p));
    return a;
}

__device__ __forceinline__ void ldsm_x4(uint32_t* r, uint32_t addr) {
    asm volatile("ldmatrix.sync.aligned.m8n8.x4.shared.b16 {%0,%1,%2,%3}, [%4];"
        : "=r"(r[0]), "=r"(r[1]), "=r"(r[2]), "=r"(r[3]) : "r"(addr));
}
__device__ __forceinline__ void ldsm_x2(uint32_t* r, uint32_t addr) {
    asm volatile("ldmatrix.sync.aligned.m8n8.x2.shared.b16 {%0,%1}, [%2];"
        : "=r"(r[0]), "=r"(r[1]) : "r"(addr));
}
__device__ __forceinline__ void ldsm_x2_trans(uint32_t* r, uint32_t addr) {
    asm volatile("ldmatrix.sync.aligned.m8n8.x2.trans.shared.b16 {%0,%1}, [%2];"
        : "=r"(r[0]), "=r"(r[1]) : "r"(addr));
}
// D += A*B, m16n8k16 bf16 -> fp32
__device__ __forceinline__ void mma_bf16(float* d, const uint32_t* a, const uint32_t* b) {
    asm volatile("mma.sync.aligned.m16n8k16.row.col.f32.bf16.bf16.f32 "
        "{%0,%1,%2,%3}, {%4,%5,%6,%7}, {%8,%9}, {%0,%1,%2,%3};"
        : "+f"(d[0]), "+f"(d[1]), "+f"(d[2]), "+f"(d[3])
        : "r"(a[0]), "r"(a[1]), "r"(a[2]), "r"(a[3]), "r"(b[0]), "r"(b[1]));
}

// split two fp32 into packed bf16x2 (hi) and bf16x2 (residual lo)
__device__ __forceinline__ void split2(float x, float y, uint32_t& hi, uint32_t& lo) {
    __nv_bfloat16 hx = __float2bfloat16_rn(x), hy = __float2bfloat16_rn(y);
    __nv_bfloat16 lx = __float2bfloat16_rn(x - __bfloat162float(hx));
    __nv_bfloat16 ly = __float2bfloat16_rn(y - __bfloat162float(hy));
    __nv_bfloat162 h = __halves2bfloat162(hx, hy);
    __nv_bfloat162 l = __halves2bfloat162(lx, ly);
    hi = *(uint32_t*)&h;
    lo = *(uint32_t*)&l;
}

// ---------------- prefix MLP kernels (tiny) ----------------
__global__ void prefix_h_kernel(const float* __restrict__ wte,
                                const float* __restrict__ w1,
                                const float* __restrict__ b1,
                                const int* __restrict__ lang) {
    int b = blockIdx.y, warp = threadIdx.x >> 5, lane = threadIdx.x & 31;
    int j = blockIdx.x * 8 + warp;
    if (j >= BOT) return;
    int L = lang[b];
    const float* e = wte + (size_t)L * D_MODEL;
    const float* w = w1 + ((size_t)L * BOT + j) * D_MODEL;
    float s = 0.f;
    for (int d = lane; d < D_MODEL; d += 32) s += e[d] * w[d];
    #pragma unroll
    for (int off = 16; off > 0; off >>= 1) s += __shfl_xor_sync(0xffffffffu, s, off);
    if (lane == 0) g_h[b * BOT + j] = tanhf(s + b1[(size_t)L * BOT + j]);
}

__global__ void prefix_kv_kernel(const float* __restrict__ w2,
                                 const float* __restrict__ b2,
                                 const int* __restrict__ lang) {
    int b = blockIdx.y, warp = threadIdx.x >> 5, lane = threadIdx.x & 31;
    int e = blockIdx.x * 8 + warp;
    int L = lang[b];
    const float* w = w2 + ((size_t)L * 2 * D_MODEL + e) * BOT;
    const float* h = g_h + b * BOT;
    float s = 0.f;
    for (int j = lane; j < BOT; j += 32) s += h[j] * w[j];
    #pragma unroll
    for (int off = 16; off > 0; off >>= 1) s += __shfl_xor_sync(0xffffffffu, s, off);
    if (lane == 0) g_pkv[b * 2 * D_MODEL + e] = s + b2[(size_t)L * 2 * D_MODEL + e];
}

// ================= mma.sync split-bf16 projection GEMM (double-buffered) =================
// C[m,n] = (sum_k A[m,k]*W[n,k] + bias[n]) * scale
// Tile: 128x128, BK=32, 256 thr / 8 warps (2x4), warp tile 64x32.
// Two smem buffers: compute(buf) overlaps convert+STS(buf^1); ONE sync per K-tile.
#define BM 128
#define BN 128
#define BK 32
#define KSTR 40
#define SM_AHI 0
#define SM_ALO (128 * KSTR)
#define SM_BHI (2 * 128 * KSTR)
#define SM_BLO (3 * 128 * KSTR)
#define GEMM_BUF_HALVES (4 * 128 * KSTR)            // 20480 halves per buffer
#define GEMM_SMEM_BYTES (2 * GEMM_BUF_HALVES * 2)   // 81920 B

#define NKT (D_MODEL / BK)   // 32

__global__ void __launch_bounds__(256, 1)
gemm_mma_kernel(const float* __restrict__ A, const float* __restrict__ W,
                const float* __restrict__ bias, float* __restrict__ C, float scale) {
    extern __shared__ __nv_bfloat16 sh[];
    uint32_t shu = smem_to_u32(sh);
    int tid = threadIdx.x, lane = tid & 31, wid = tid >> 5;
    int m0 = blockIdx.y * BM, n0 = blockIdx.x * BN;
    int mw = (wid & 1) * 64, nw = (wid >> 1) * 32;
    int lr = tid >> 3, lkc = (tid & 7) * 4;   // per-thread load row / k-col

    float acc[4][4][4];
    #pragma unroll
    for (int i = 0; i < 4; i++)
        #pragma unroll
        for (int j = 0; j < 4; j++)
            #pragma unroll
            for (int c = 0; c < 4; c++) acc[i][j][c] = 0.f;

    // ---- prologue: load + convert tile 0 into buffer 0 ----
    {
        #pragma unroll
        for (int i = 0; i < 4; i++) {
            int r = lr + i * 32;
            float4 fa = *(const float4*)(A + (size_t)(m0 + r) * D_MODEL + lkc);
            float4 fw = *(const float4*)(W + (size_t)(n0 + r) * D_MODEL + lkc);
            uint32_t h0, l0, h1, l1;
            split2(fa.x, fa.y, h0, l0);
            split2(fa.z, fa.w, h1, l1);
            *(uint2*)(sh + SM_AHI + r * KSTR + lkc) = make_uint2(h0, h1);
            *(uint2*)(sh + SM_ALO + r * KSTR + lkc) = make_uint2(l0, l1);
            split2(fw.x, fw.y, h0, l0);
            split2(fw.z, fw.w, h1, l1);
            *(uint2*)(sh + SM_BHI + r * KSTR + lkc) = make_uint2(h0, h1);
            *(uint2*)(sh + SM_BLO + r * KSTR + lkc) = make_uint2(l0, l1);
        }
    }
    __syncthreads();

    for (int it = 0; it < NKT; it++) {
        int buf = it & 1;
        uint32_t bufu = shu + (uint32_t)(buf * GEMM_BUF_HALVES * 2);
        __nv_bfloat16* nxt = sh + ((buf ^ 1) * GEMM_BUF_HALVES);

        // ---- prefetch next tile to regs (LDG issues before compute) ----
        float4 ra[4], rw[4];
        bool have_next = (it + 1 < NKT);
        if (have_next) {
            int k0n = (it + 1) * BK;
            #pragma unroll
            for (int i = 0; i < 4; i++) {
                int r = lr + i * 32;
                ra[i] = *(const float4*)(A + (size_t)(m0 + r) * D_MODEL + k0n + lkc);
                rw[i] = *(const float4*)(W + (size_t)(n0 + r) * D_MODEL + k0n + lkc);
            }
        }

        // ---- compute from current buffer ----
        #pragma unroll
        for (int ks = 0; ks < BK; ks += 16) {
            uint32_t ahi[4][4], alo[4][4], bhi[4][2], blo[4][2];
            int arow = mw + (lane & 15);
            int acol = ks + (lane >> 4) * 8;
            #pragma unroll
            for (int mt = 0; mt < 4; mt++) {
                uint32_t off = (uint32_t)(((arow + mt * 16) * KSTR + acol) * 2);
                ldsm_x4(ahi[mt], bufu + SM_AHI * 2 + off);
                ldsm_x4(alo[mt], bufu + SM_ALO * 2 + off);
            }
            int brow = nw + (lane & 7);
            int bcol = ks + ((lane >> 3) & 1) * 8;
            #pragma unroll
            for (int nt = 0; nt < 4; nt++) {
                uint32_t off = (uint32_t)(((brow + nt * 8) * KSTR + bcol) * 2);
                ldsm_x2(bhi[nt], bufu + SM_BHI * 2 + off);
                ldsm_x2(blo[nt], bufu + SM_BLO * 2 + off);
            }
            #pragma unroll
            for (int mt = 0; mt < 4; mt++)
                #pragma unroll
                for (int nt = 0; nt < 4; nt++) {
                    mma_bf16(acc[mt][nt], ahi[mt], bhi[nt]);
                    mma_bf16(acc[mt][nt], ahi[mt], blo[nt]);
                    mma_bf16(acc[mt][nt], alo[mt], bhi[nt]);
                }
        }

        // ---- convert + STS next tile into the other buffer ----
        if (have_next) {
            #pragma unroll
            for (int i = 0; i < 4; i++) {
                int r = lr + i * 32;
                uint32_t h0, l0, h1, l1;
                split2(ra[i].x, ra[i].y, h0, l0);
                split2(ra[i].z, ra[i].w, h1, l1);
                *(uint2*)(nxt + SM_AHI + r * KSTR + lkc) = make_uint2(h0, h1);
                *(uint2*)(nxt + SM_ALO + r * KSTR + lkc) = make_uint2(l0, l1);
                split2(rw[i].x, rw[i].y, h0, l0);
                split2(rw[i].z, rw[i].w, h1, l1);
                *(uint2*)(nxt + SM_BHI + r * KSTR + lkc) = make_uint2(h0, h1);
                *(uint2*)(nxt + SM_BLO + r * KSTR + lkc) = make_uint2(l0, l1);
            }
        }
        __syncthreads();
    }

    // --- epilogue: frag layout c0,c1 @ (row=lane/4, col=2*(lane%4)), c2,c3 @ row+8 ---
    #pragma unroll
    for (int mt = 0; mt < 4; mt++) {
        int r0 = m0 + mw + mt * 16 + (lane >> 2);
        #pragma unroll
        for (int nt = 0; nt < 4; nt++) {
            int c = n0 + nw + nt * 8 + (lane & 3) * 2;
            float2 bb = *(const float2*)(bias + c);
            float2 o0, o1;
            o0.x = (acc[mt][nt][0] + bb.x) * scale;
            o0.y = (acc[mt][nt][1] + bb.y) * scale;
            o1.x = (acc[mt][nt][2] + bb.x) * scale;
            o1.y = (acc[mt][nt][3] + bb.y) * scale;
            *(float2*)(C + (size_t)r0 * D_MODEL + c) = o0;
            *(float2*)(C + (size_t)(r0 + 8) * D_MODEL + c) = o1;
        }
    }
}

// ================= mma.sync flash attention (split-bf16, unchanged) =================
#define A_STR 72
#define AQHI 0
#define AQLO (128 * A_STR)
#define AKHI (2 * 128 * A_STR)
#define AKLO (AKHI + 64 * A_STR)
#define AVHI (AKLO + 64 * A_STR)
#define AVLO (AVHI + 64 * A_STR)
#define ATT_SMEM_HALVES (AVLO + 64 * A_STR) // 36864 halves = 73728 B

__global__ void __launch_bounds__(256, 1)
attn_mma_kernel(void) {
    extern __shared__ __nv_bfloat16 ash[];
    uint32_t shu = smem_to_u32(ash);
    int b = blockIdx.z, h = blockIdx.y;
    int t0 = blockIdx.x * 128;
    int tid = threadIdx.x, lane = tid & 31, wid = tid >> 5;

    const float* qbase = g_q + (size_t)t0 * BD + b * D_MODEL + h * HD;
    const float* kbase = g_k + (size_t)b * D_MODEL + h * HD;
    const float* vbase = g_v + (size_t)b * D_MODEL + h * HD;

    // ---- load Q tile (128x64) split into smem ----
    {
        int row = tid >> 1, c0 = (tid & 1) * 32;
        const float* qp = qbase + (size_t)row * BD + c0;
        #pragma unroll
        for (int i = 0; i < 8; i++) {
            float4 f = *(const float4*)(qp + i * 4);
            uint32_t h0, l0, h1, l1;
            split2(f.x, f.y, h0, l0);
            split2(f.z, f.w, h1, l1);
            int off = row * A_STR + c0 + i * 4;
            *(uint32_t*)(ash + AQHI + off) = h0;
            *(uint32_t*)(ash + AQHI + off + 2) = h1;
            *(uint32_t*)(ash + AQLO + off) = l0;
            *(uint32_t*)(ash + AQLO + off + 2) = l1;
        }
    }

    // ---- prefix token ----
    const float* pk = g_pkv + b * 2 * D_MODEL + h * HD;
    const float* pv = pk + D_MODEL;
    int r0 = wid * 16 + (lane >> 2);
    int r1 = r0 + 8;
    float m0, m1, l0 = 1.f, l1 = 1.f;
    {
        float s0 = 0.f, s1 = 0.f;
        const float* q0 = qbase + (size_t)r0 * BD;
        const float* q1 = qbase + (size_t)r1 * BD;
        #pragma unroll 8
        for (int d = 0; d < HD; d++) {
            float kv = pk[d];
            s0 += q0[d] * kv;
            s1 += q1[d] * kv;
        }
        m0 = s0; m1 = s1;
    }
    float O[8][4];
    #pragma unroll
    for (int nt = 0; nt < 8; nt++) {
        int c = nt * 8 + (lane & 3) * 2;
        O[nt][0] = pv[c];     O[nt][1] = pv[c + 1];
        O[nt][2] = pv[c];     O[nt][3] = pv[c + 1];
    }

    // ---- mainloop over 32 K-tiles of 64 keys ----
    for (int kt = 0; kt < T_LEN / 64; kt++) {
        __syncthreads();
        {
            int key = tid >> 2, c0 = (tid & 3) * 16;
            const float* kp = kbase + (size_t)(kt * 64 + key) * BD + c0;
            #pragma unroll
            for (int i = 0; i < 4; i++) {
                float4 f = *(const float4*)(kp + i * 4);
                uint32_t h0, l0r, h1, l1r;
                split2(f.x, f.y, h0, l0r);
                split2(f.z, f.w, h1, l1r);
                int off = key * A_STR + c0 + i * 4;
                *(uint32_t*)(ash + AKHI + off) = h0;
                *(uint32_t*)(ash + AKHI + off + 2) = h1;
                *(uint32_t*)(ash + AKLO + off) = l0r;
                *(uint32_t*)(ash + AKLO + off + 2) = l1r;
            }
        }
        {
            int key = tid >> 2, c0 = (tid & 3) * 16;
            const float* vp = vbase + (size_t)(kt * 64 + key) * BD + c0;
            #pragma unroll
            for (int i = 0; i < 4; i++) {
                float4 f = *(const float4*)(vp + i * 4);
                uint32_t h0, l0r, h1, l1r;
                split2(f.x, f.y, h0, l0r);
                split2(f.z, f.w, h1, l1r);
                int off = key * A_STR + c0 + i * 4;
                *(uint32_t*)(ash + AVHI + off) = h0;
                *(uint32_t*)(ash + AVHI + off + 2) = h1;
                *(uint32_t*)(ash + AVLO + off) = l0r;
                *(uint32_t*)(ash + AVLO + off + 2) = l1r;
            }
        }
        __syncthreads();

        // ---- S = Q @ K^T ----
        float s[8][4];
        #pragma unroll
        for (int nt = 0; nt < 8; nt++)
            #pragma unroll
            for (int c = 0; c < 4; c++) s[nt][c] = 0.f;

        #pragma unroll
        for (int ks = 0; ks < 4; ks++) {
            uint32_t ahi[4], alo[4];
            int ar = wid * 16 + (lane & 15);
            int ac = ks * 16 + (lane >> 4) * 8;
            uint32_t aoff = (uint32_t)((ar * A_STR + ac) * 2);
            ldsm_x4(ahi, shu + AQHI * 2 + aoff);
            ldsm_x4(alo, shu + AQLO * 2 + aoff);
            #pragma unroll
            for (int nt = 0; nt < 8; nt++) {
                int br = nt * 8 + (lane & 7);
                int bc = ks * 16 + ((lane >> 3) & 1) * 8;
                uint32_t boff = (uint32_t)((br * A_STR + bc) * 2);
                uint32_t bhi[2], blo[2];
                ldsm_x2(bhi, shu + AKHI * 2 + boff);
                ldsm_x2(blo, shu + AKLO * 2 + boff);
                mma_bf16(s[nt], ahi, bhi);
                mma_bf16(s[nt], ahi, blo);
                mma_bf16(s[nt], alo, bhi);
            }
        }

        // ---- online softmax ----
        float mx0 = s[0][0], mx1 = s[0][2];
        #pragma unroll
        for (int nt = 0; nt < 8; nt++) {
            mx0 = fmaxf(mx0, fmaxf(s[nt][0], s[nt][1]));
            mx1 = fmaxf(mx1, fmaxf(s[nt][2], s[nt][3]));
        }
        mx0 = fmaxf(mx0, __shfl_xor_sync(0xffffffffu, mx0, 1));
        mx0 = fmaxf(mx0, __shfl_xor_sync(0xffffffffu, mx0, 2));
        mx1 = fmaxf(mx1, __shfl_xor_sync(0xffffffffu, mx1, 1));
        mx1 = fmaxf(mx1, __shfl_xor_sync(0xffffffffu, mx1, 2));
        float mn0 = fmaxf(m0, mx0), mn1 = fmaxf(m1, mx1);
        float f0 = __expf(m0 - mn0), f1 = __expf(m1 - mn1);
        m0 = mn0; m1 = mn1;
        float sum0 = 0.f, sum1 = 0.f;
        #pragma unroll
        for (int nt = 0; nt < 8; nt++) {
            s[nt][0] = __expf(s[nt][0] - mn0);
            s[nt][1] = __expf(s[nt][1] - mn0);
            s[nt][2] = __expf(s[nt][2] - mn1);
            s[nt][3] = __expf(s[nt][3] - mn1);
            sum0 += s[nt][0] + s[nt][1];
            sum1 += s[nt][2] + s[nt][3];
        }
        sum0 += __shfl_xor_sync(0xffffffffu, sum0, 1);
        sum0 += __shfl_xor_sync(0xffffffffu, sum0, 2);
        sum1 += __shfl_xor_sync(0xffffffffu, sum1, 1);
        sum1 += __shfl_xor_sync(0xffffffffu, sum1, 2);
        l0 = l0 * f0 + sum0;
        l1 = l1 * f1 + sum1;
        #pragma unroll
        for (int nt = 0; nt < 8; nt++) {
            O[nt][0] *= f0; O[nt][1] *= f0;
            O[nt][2] *= f1; O[nt][3] *= f1;
        }

        // ---- O += P @ V ----
        #pragma unroll
        for (int kc = 0; kc < 4; kc++) {
            uint32_t phi[4], plo[4];
            split2(s[2 * kc][0],     s[2 * kc][1],     phi[0], plo[0]);
            split2(s[2 * kc][2],     s[2 * kc][3],     phi[1], plo[1]);
            split2(s[2 * kc + 1][0], s[2 * kc + 1][1], phi[2], plo[2]);
            split2(s[2 * kc + 1][2], s[2 * kc + 1][3], phi[3], plo[3]);
            #pragma unroll
            for (int nt = 0; nt < 8; nt++) {
                int vr = kc * 16 + (lane & 15);
                uint32_t boff = (uint32_t)((vr * A_STR + nt * 8) * 2);
                uint32_t bhi[2], blo[2];
                ldsm_x2_trans(bhi, shu + AVHI * 2 + boff);
                ldsm_x2_trans(blo, shu + AVLO * 2 + boff);
                mma_bf16(O[nt], phi, bhi);
                mma_bf16(O[nt], phi, blo);
                mma_bf16(O[nt], plo, bhi);
            }
        }
    }

    // ---- epilogue ----
    float inv0 = 1.0f / l0, inv1 = 1.0f / l1;
    #pragma unroll
    for (int nt = 0; nt < 8; nt++) {
        int c = h * HD + nt * 8 + (lane & 3) * 2;
        float2 o0, o1;
        o0.x = O[nt][0] * inv0; o0.y = O[nt][1] * inv0;
        o1.x = O[nt][2] * inv1; o1.y = O[nt][3] * inv1;
        *(float2*)(g_ctx + (size_t)(t0 + r0) * BD + b * D_MODEL + c) = o0;
        *(float2*)(g_ctx + (size_t)(t0 + r1) * BD + b * D_MODEL + c) = o1;
    }
}

// ---------------- launch ----------------
extern "C" void kernel_launch(void* const* d_in, const int* in_sizes, int n_in,
                              void* d_out, int out_size) {
    const float* query = (const float*)d_in[0];
    const float* key   = (const float*)d_in[1];
    const float* value = (const float*)d_in[2];
    const float* wq    = (const float*)d_in[3];
    const float* bq    = (const float*)d_in[4];
    const float* wk    = (const float*)d_in[5];
    const float* bk    = (const float*)d_in[6];
    const float* wv    = (const float*)d_in[7];
    const float* bv    = (const float*)d_in[8];
    const float* wo    = (const float*)d_in[9];
    const float* bo    = (const float*)d_in[10];
    const float* wte   = (const float*)d_in[11];
    const float* ct_w1 = (const float*)d_in[12];
    const float* ct_b1 = (const float*)d_in[13];
    const float* ct_w2 = (const float*)d_in[14];
    const float* ct_b2 = (const float*)d_in[15];
    const int*   lang  = (const int*)d_in[16];
    float* out = (float*)d_out;

    (void)in_sizes; (void)n_in; (void)out_size;

    prefix_h_kernel<<<dim3(100, BATCH), 256>>>(wte, ct_w1, ct_b1, lang);
    prefix_kv_kernel<<<dim3(256, BATCH), 256>>>(ct_w2, ct_b2, lang);

    float* dq; cudaGetSymbolAddress((void**)&dq, g_q);
    float* dk; cudaGetSymbolAddress((void**)&dk, g_k);
    float* dv; cudaGetSymbolAddress((void**)&dv, g_v);
    float* dctx; cudaGetSymbolAddress((void**)&dctx, g_ctx);

    cudaFuncSetAttribute(gemm_mma_kernel, cudaFuncAttributeMaxDynamicSharedMemorySize,
                         GEMM_SMEM_BYTES);
    dim3 ggrid(D_MODEL / BN, ROWS / BM);   // (8, 32)
    gemm_mma_kernel<<<ggrid, 256, GEMM_SMEM_BYTES>>>(query, wq, bq, dq, SCALING);
    gemm_mma_kernel<<<ggrid, 256, GEMM_SMEM_BYTES>>>(key,   wk, bk, dk, 1.0f);
    gemm_mma_kernel<<<ggrid, 256, GEMM_SMEM_BYTES>>>(value, wv, bv, dv, 1.0f);

    size_t att_smem = ATT_SMEM_HALVES * sizeof(__nv_bfloat16);   // 73728 B
    cudaFuncSetAttribute(attn_mma_kernel, cudaFuncAttributeMaxDynamicSharedMemorySize,
                         (int)att_smem);
    attn_mma_kernel<<<dim3(T_LEN / 128, NHEAD, BATCH), 256, att_smem>>>();

    gemm_mma_kernel<<<ggrid, 256, GEMM_SMEM_BYTES>>>(dctx, wo, bo, out, 1.0f);
}

// round 17
// speedup vs baseline: 3.1225x; 1.0424x over previous
#include <cuda_runtime.h>
#include <cuda_bf16.h>
#include <math.h>
#include <stdint.h>

// ---------------- problem dims (fixed by setup_inputs) ----------------
#define T_LEN   2048
#define BATCH   2
#define D_MODEL 1024
#define NHEAD   16
#define HD      64
#define VOCAB   5
#define BOT     800
#define SCALING 0.125f
#define BD      (BATCH * D_MODEL)
#define ROWS    (T_LEN * BATCH)      // 4096

// ---------------- scratch (static device memory; no allocs) ----------------
__device__ __align__(256) float g_q[ROWS * D_MODEL];
__device__ __align__(256) float g_k[ROWS * D_MODEL];
__device__ __align__(256) float g_v[ROWS * D_MODEL];
__device__ __align__(256) float g_ctx[ROWS * D_MODEL];
__device__ __align__(256) float g_h[BATCH * BOT];
__device__ __align__(256) float g_pkv[BATCH * 2 * D_MODEL];

// ================= helpers =================
__device__ __forceinline__ uint32_t smem_to_u32(const void* p) {
    uint32_t a;
    asm("{ .reg .u64 t; cvta.to.shared.u64 t, %1; cvt.u32.u64 %0, t; }" : "=r"(a) : "l"(p));
    return a;
}

__device__ __forceinline__ void ldsm_x4(uint32_t* r, uint32_t addr) {
    asm volatile("ldmatrix.sync.aligned.m8n8.x4.shared.b16 {%0,%1,%2,%3}, [%4];"
        : "=r"(r[0]), "=r"(r[1]), "=r"(r[2]), "=r"(r[3]) : "r"(addr));
}
__device__ __forceinline__ void ldsm_x2(uint32_t* r, uint32_t addr) {
    asm volatile("ldmatrix.sync.aligned.m8n8.x2.shared.b16 {%0,%1}, [%2];"
        : "=r"(r[0]), "=r"(r[1]) : "r"(addr));
}
__device__ __forceinline__ void ldsm_x2_trans(uint32_t* r, uint32_t addr) {
    asm volatile("ldmatrix.sync.aligned.m8n8.x2.trans.shared.b16 {%0,%1}, [%2];"
        : "=r"(r[0]), "=r"(r[1]) : "r"(addr));
}
// D += A*B, m16n8k16 bf16 -> fp32
__device__ __forceinline__ void mma_bf16(float* d, const uint32_t* a, const uint32_t* b) {
    asm volatile("mma.sync.aligned.m16n8k16.row.col.f32.bf16.bf16.f32 "
        "{%0,%1,%2,%3}, {%4,%5,%6,%7}, {%8,%9}, {%0,%1,%2,%3};"
        : "+f"(d[0]), "+f"(d[1]), "+f"(d[2]), "+f"(d[3])
        : "r"(a[0]), "r"(a[1]), "r"(a[2]), "r"(a[3]), "r"(b[0]), "r"(b[1]));
}

// split two fp32 into packed bf16x2 (hi) and bf16x2 (residual lo)
__device__ __forceinline__ void split2(float x, float y, uint32_t& hi, uint32_t& lo) {
    __nv_bfloat16 hx = __float2bfloat16_rn(x), hy = __float2bfloat16_rn(y);
    __nv_bfloat16 lx = __float2bfloat16_rn(x - __bfloat162float(hx));
    __nv_bfloat16 ly = __float2bfloat16_rn(y - __bfloat162float(hy));
    __nv_bfloat162 h = __halves2bfloat162(hx, hy);
    __nv_bfloat162 l = __halves2bfloat162(lx, ly);
    hi = *(uint32_t*)&h;
    lo = *(uint32_t*)&l;
}

// ---------------- prefix MLP kernels (tiny) ----------------
__global__ void prefix_h_kernel(const float* __restrict__ wte,
                                const float* __restrict__ w1,
                                const float* __restrict__ b1,
                                const int* __restrict__ lang) {
    int b = blockIdx.y, warp = threadIdx.x >> 5, lane = threadIdx.x & 31;
    int j = blockIdx.x * 8 + warp;
    if (j >= BOT) return;
    int L = lang[b];
    const float* e = wte + (size_t)L * D_MODEL;
    const float* w = w1 + ((size_t)L * BOT + j) * D_MODEL;
    float s = 0.f;
    for (int d = lane; d < D_MODEL; d += 32) s += e[d] * w[d];
    #pragma unroll
    for (int off = 16; off > 0; off >>= 1) s += __shfl_xor_sync(0xffffffffu, s, off);
    if (lane == 0) g_h[b * BOT + j] = tanhf(s + b1[(size_t)L * BOT + j]);
}

__global__ void prefix_kv_kernel(const float* __restrict__ w2,
                                 const float* __restrict__ b2,
                                 const int* __restrict__ lang) {
    int b = blockIdx.y, warp = threadIdx.x >> 5, lane = threadIdx.x & 31;
    int e = blockIdx.x * 8 + warp;
    int L = lang[b];
    const float* w = w2 + ((size_t)L * 2 * D_MODEL + e) * BOT;
    const float* h = g_h + b * BOT;
    float s = 0.f;
    for (int j = lane; j < BOT; j += 32) s += h[j] * w[j];
    #pragma unroll
    for (int off = 16; off > 0; off >>= 1) s += __shfl_xor_sync(0xffffffffu, s, off);
    if (lane == 0) g_pkv[b * 2 * D_MODEL + e] = s + b2[(size_t)L * 2 * D_MODEL + e];
}

// ================= mma.sync split-bf16 projection GEMM (double-buffered, UNCHANGED) ======
#define BM 128
#define BN 128
#define BK 32
#define KSTR 40
#define SM_AHI 0
#define SM_ALO (128 * KSTR)
#define SM_BHI (2 * 128 * KSTR)
#define SM_BLO (3 * 128 * KSTR)
#define GEMM_BUF_HALVES (4 * 128 * KSTR)
#define GEMM_SMEM_BYTES (2 * GEMM_BUF_HALVES * 2)   // 81920 B

#define NKT (D_MODEL / BK)   // 32

__global__ void __launch_bounds__(256, 1)
gemm_mma_kernel(const float* __restrict__ A, const float* __restrict__ W,
                const float* __restrict__ bias, float* __restrict__ C, float scale) {
    extern __shared__ __nv_bfloat16 sh[];
    uint32_t shu = smem_to_u32(sh);
    int tid = threadIdx.x, lane = tid & 31, wid = tid >> 5;
    int m0 = blockIdx.y * BM, n0 = blockIdx.x * BN;
    int mw = (wid & 1) * 64, nw = (wid >> 1) * 32;
    int lr = tid >> 3, lkc = (tid & 7) * 4;

    float acc[4][4][4];
    #pragma unroll
    for (int i = 0; i < 4; i++)
        #pragma unroll
        for (int j = 0; j < 4; j++)
            #pragma unroll
            for (int c = 0; c < 4; c++) acc[i][j][c] = 0.f;

    {
        #pragma unroll
        for (int i = 0; i < 4; i++) {
            int r = lr + i * 32;
            float4 fa = *(const float4*)(A + (size_t)(m0 + r) * D_MODEL + lkc);
            float4 fw = *(const float4*)(W + (size_t)(n0 + r) * D_MODEL + lkc);
            uint32_t h0, l0, h1, l1;
            split2(fa.x, fa.y, h0, l0);
            split2(fa.z, fa.w, h1, l1);
            *(uint2*)(sh + SM_AHI + r * KSTR + lkc) = make_uint2(h0, h1);
            *(uint2*)(sh + SM_ALO + r * KSTR + lkc) = make_uint2(l0, l1);
            split2(fw.x, fw.y, h0, l0);
            split2(fw.z, fw.w, h1, l1);
            *(uint2*)(sh + SM_BHI + r * KSTR + lkc) = make_uint2(h0, h1);
            *(uint2*)(sh + SM_BLO + r * KSTR + lkc) = make_uint2(l0, l1);
        }
    }
    __syncthreads();

    for (int it = 0; it < NKT; it++) {
        int buf = it & 1;
        uint32_t bufu = shu + (uint32_t)(buf * GEMM_BUF_HALVES * 2);
        __nv_bfloat16* nxt = sh + ((buf ^ 1) * GEMM_BUF_HALVES);

        float4 ra[4], rw[4];
        bool have_next = (it + 1 < NKT);
        if (have_next) {
            int k0n = (it + 1) * BK;
            #pragma unroll
            for (int i = 0; i < 4; i++) {
                int r = lr + i * 32;
                ra[i] = *(const float4*)(A + (size_t)(m0 + r) * D_MODEL + k0n + lkc);
                rw[i] = *(const float4*)(W + (size_t)(n0 + r) * D_MODEL + k0n + lkc);
            }
        }

        #pragma unroll
        for (int ks = 0; ks < BK; ks += 16) {
            uint32_t ahi[4][4], alo[4][4], bhi[4][2], blo[4][2];
            int arow = mw + (lane & 15);
            int acol = ks + (lane >> 4) * 8;
            #pragma unroll
            for (int mt = 0; mt < 4; mt++) {
                uint32_t off = (uint32_t)(((arow + mt * 16) * KSTR + acol) * 2);
                ldsm_x4(ahi[mt], bufu + SM_AHI * 2 + off);
                ldsm_x4(alo[mt], bufu + SM_ALO * 2 + off);
            }
            int brow = nw + (lane & 7);
            int bcol = ks + ((lane >> 3) & 1) * 8;
            #pragma unroll
            for (int nt = 0; nt < 4; nt++) {
                uint32_t off = (uint32_t)(((brow + nt * 8) * KSTR + bcol) * 2);
                ldsm_x2(bhi[nt], bufu + SM_BHI * 2 + off);
                ldsm_x2(blo[nt], bufu + SM_BLO * 2 + off);
            }
            #pragma unroll
            for (int mt = 0; mt < 4; mt++)
                #pragma unroll
                for (int nt = 0; nt < 4; nt++) {
                    mma_bf16(acc[mt][nt], ahi[mt], bhi[nt]);
                    mma_bf16(acc[mt][nt], ahi[mt], blo[nt]);
                    mma_bf16(acc[mt][nt], alo[mt], bhi[nt]);
                }
        }

        if (have_next) {
            #pragma unroll
            for (int i = 0; i < 4; i++) {
                int r = lr + i * 32;
                uint32_t h0, l0, h1, l1;
                split2(ra[i].x, ra[i].y, h0, l0);
                split2(ra[i].z, ra[i].w, h1, l1);
                *(uint2*)(nxt + SM_AHI + r * KSTR + lkc) = make_uint2(h0, h1);
                *(uint2*)(nxt + SM_ALO + r * KSTR + lkc) = make_uint2(l0, l1);
                split2(rw[i].x, rw[i].y, h0, l0);
                split2(rw[i].z, rw[i].w, h1, l1);
                *(uint2*)(nxt + SM_BHI + r * KSTR + lkc) = make_uint2(h0, h1);
                *(uint2*)(nxt + SM_BLO + r * KSTR + lkc) = make_uint2(l0, l1);
            }
        }
        __syncthreads();
    }

    #pragma unroll
    for (int mt = 0; mt < 4; mt++) {
        int r0 = m0 + mw + mt * 16 + (lane >> 2);
        #pragma unroll
        for (int nt = 0; nt < 4; nt++) {
            int c = n0 + nw + nt * 8 + (lane & 3) * 2;
            float2 bb = *(const float2*)(bias + c);
            float2 o0, o1;
            o0.x = (acc[mt][nt][0] + bb.x) * scale;
            o0.y = (acc[mt][nt][1] + bb.y) * scale;
            o1.x = (acc[mt][nt][2] + bb.x) * scale;
            o1.y = (acc[mt][nt][3] + bb.y) * scale;
            *(float2*)(C + (size_t)r0 * D_MODEL + c) = o0;
            *(float2*)(C + (size_t)(r0 + 8) * D_MODEL + c) = o1;
        }
    }
}

// ================= mma.sync flash attention (split-bf16, DOUBLE-BUFFERED K/V) =============
// Q (hi,lo) resident; K/V tiles (64 keys) double-buffered.
// Per tile: prefetch K(kt+1) -> S MMAs -> STS K -> prefetch V(kt+1) -> softmax
//           -> P@V MMAs -> STS V -> one __syncthreads.
#define A_STR 72
#define AQHI 0
#define AQLO (128 * A_STR)                      // 9216
#define AKV0 (2 * 128 * A_STR)                  // 18432 (buffer 0 start)
#define KVBUF (4 * 64 * A_STR)                  // 18432 halves per buffer
#define KHI_OFF 0
#define KLO_OFF (64 * A_STR)                    // 4608
#define VHI_OFF (2 * 64 * A_STR)                // 9216
#define VLO_OFF (3 * 64 * A_STR)                // 13824
#define ATT_SMEM_HALVES (AKV0 + 2 * KVBUF)      // 55296 halves = 110592 B
#define NT_ATT (T_LEN / 64)                     // 32

__global__ void __launch_bounds__(256, 1)
attn_mma_kernel(void) {
    extern __shared__ __nv_bfloat16 ash[];
    uint32_t shu = smem_to_u32(ash);
    int b = blockIdx.z, h = blockIdx.y;
    int t0 = blockIdx.x * 128;
    int tid = threadIdx.x, lane = tid & 31, wid = tid >> 5;

    const float* qbase = g_q + (size_t)t0 * BD + b * D_MODEL + h * HD;
    const float* kbase = g_k + (size_t)b * D_MODEL + h * HD;
    const float* vbase = g_v + (size_t)b * D_MODEL + h * HD;

    int lkey = tid >> 2, lc0 = (tid & 3) * 16;   // per-thread K/V load coords

    // ---- load Q tile (128x64) split into smem ----
    {
        int row = tid >> 1, c0 = (tid & 1) * 32;
        const float* qp = qbase + (size_t)row * BD + c0;
        #pragma unroll
        for (int i = 0; i < 8; i++) {
            float4 f = *(const float4*)(qp + i * 4);
            uint32_t h0, l0, h1, l1;
            split2(f.x, f.y, h0, l0);
            split2(f.z, f.w, h1, l1);
            int off = row * A_STR + c0 + i * 4;
            *(uint32_t*)(ash + AQHI + off) = h0;
            *(uint32_t*)(ash + AQHI + off + 2) = h1;
            *(uint32_t*)(ash + AQLO + off) = l0;
            *(uint32_t*)(ash + AQLO + off + 2) = l1;
        }
    }

    // ---- prologue: K/V tile 0 into buffer 0 ----
    {
        __nv_bfloat16* b0 = ash + AKV0;
        const float* kp = kbase + (size_t)lkey * BD + lc0;
        const float* vp = vbase + (size_t)lkey * BD + lc0;
        #pragma unroll
        for (int i = 0; i < 4; i++) {
            float4 f = *(const float4*)(kp + i * 4);
            uint32_t h0, l0r, h1, l1r;
            split2(f.x, f.y, h0, l0r);
            split2(f.z, f.w, h1, l1r);
            int off = lkey * A_STR + lc0 + i * 4;
            *(uint2*)(b0 + KHI_OFF + off) = make_uint2(h0, h1);
            *(uint2*)(b0 + KLO_OFF + off) = make_uint2(l0r, l1r);
            float4 g = *(const float4*)(vp + i * 4);
            split2(g.x, g.y, h0, l0r);
            split2(g.z, g.w, h1, l1r);
            *(uint2*)(b0 + VHI_OFF + off) = make_uint2(h0, h1);
            *(uint2*)(b0 + VLO_OFF + off) = make_uint2(l0r, l1r);
        }
    }

    // ---- prefix token ----
    const float* pk = g_pkv + b * 2 * D_MODEL + h * HD;
    const float* pv = pk + D_MODEL;
    int r0 = wid * 16 + (lane >> 2);
    int r1 = r0 + 8;
    float m0, m1, l0 = 1.f, l1 = 1.f;
    {
        float s0 = 0.f, s1 = 0.f;
        const float* q0 = qbase + (size_t)r0 * BD;
        const float* q1 = qbase + (size_t)r1 * BD;
        #pragma unroll 8
        for (int d = 0; d < HD; d++) {
            float kv = pk[d];
            s0 += q0[d] * kv;
            s1 += q1[d] * kv;
        }
        m0 = s0; m1 = s1;
    }
    float O[8][4];
    #pragma unroll
    for (int nt = 0; nt < 8; nt++) {
        int c = nt * 8 + (lane & 3) * 2;
        O[nt][0] = pv[c];     O[nt][1] = pv[c + 1];
        O[nt][2] = pv[c];     O[nt][3] = pv[c + 1];
    }
    __syncthreads();   // Q + tile 0 visible

    // ---- mainloop ----
    for (int kt = 0; kt < NT_ATT; kt++) {
        int buf = kt & 1;
        uint32_t kvu = shu + (uint32_t)((AKV0 + buf * KVBUF) * 2);
        __nv_bfloat16* nxt = ash + AKV0 + (buf ^ 1) * KVBUF;
        bool have_next = (kt + 1 < NT_ATT);

        // ---- prefetch K(kt+1) to regs ----
        float4 kf[4];
        if (have_next) {
            const float* kp = kbase + (size_t)((kt + 1) * 64 + lkey) * BD + lc0;
            #pragma unroll
            for (int i = 0; i < 4; i++) kf[i] = *(const float4*)(kp + i * 4);
        }

        // ---- S = Q @ K^T ----
        float s[8][4];
        #pragma unroll
        for (int nt = 0; nt < 8; nt++)
            #pragma unroll
            for (int c = 0; c < 4; c++) s[nt][c] = 0.f;

        #pragma unroll
        for (int ks = 0; ks < 4; ks++) {
            uint32_t ahi[4], alo[4];
            int ar = wid * 16 + (lane & 15);
            int ac = ks * 16 + (lane >> 4) * 8;
            uint32_t aoff = (uint32_t)((ar * A_STR + ac) * 2);
            ldsm_x4(ahi, shu + AQHI * 2 + aoff);
            ldsm_x4(alo, shu + AQLO * 2 + aoff);
            #pragma unroll
            for (int nt = 0; nt < 8; nt++) {
                int br = nt * 8 + (lane & 7);
                int bc = ks * 16 + ((lane >> 3) & 1) * 8;
                uint32_t boff = (uint32_t)((br * A_STR + bc) * 2);
                uint32_t bhi[2], blo[2];
                ldsm_x2(bhi, kvu + KHI_OFF * 2 + boff);
                ldsm_x2(blo, kvu + KLO_OFF * 2 + boff);
                mma_bf16(s[nt], ahi, bhi);
                mma_bf16(s[nt], ahi, blo);
                mma_bf16(s[nt], alo, bhi);
            }
        }

        // ---- STS K(kt+1) into other buffer (K of current tile is dead) ----
        if (have_next) {
            #pragma unroll
            for (int i = 0; i < 4; i++) {
                uint32_t h0, l0r, h1, l1r;
                split2(kf[i].x, kf[i].y, h0, l0r);
                split2(kf[i].z, kf[i].w, h1, l1r);
                int off = lkey * A_STR + lc0 + i * 4;
                *(uint2*)(nxt + KHI_OFF + off) = make_uint2(h0, h1);
                *(uint2*)(nxt + KLO_OFF + off) = make_uint2(l0r, l1r);
            }
        }

        // ---- prefetch V(kt+1) to regs (latency hides under softmax) ----
        float4 vf[4];
        if (have_next) {
            const float* vp = vbase + (size_t)((kt + 1) * 64 + lkey) * BD + lc0;
            #pragma unroll
            for (int i = 0; i < 4; i++) vf[i] = *(const float4*)(vp + i * 4);
        }

        // ---- online softmax ----
        float mx0 = s[0][0], mx1 = s[0][2];
        #pragma unroll
        for (int nt = 0; nt < 8; nt++) {
            mx0 = fmaxf(mx0, fmaxf(s[nt][0], s[nt][1]));
            mx1 = fmaxf(mx1, fmaxf(s[nt][2], s[nt][3]));
        }
        mx0 = fmaxf(mx0, __shfl_xor_sync(0xffffffffu, mx0, 1));
        mx0 = fmaxf(mx0, __shfl_xor_sync(0xffffffffu, mx0, 2));
        mx1 = fmaxf(mx1, __shfl_xor_sync(0xffffffffu, mx1, 1));
        mx1 = fmaxf(mx1, __shfl_xor_sync(0xffffffffu, mx1, 2));
        float mn0 = fmaxf(m0, mx0), mn1 = fmaxf(m1, mx1);
        float f0 = __expf(m0 - mn0), f1 = __expf(m1 - mn1);
        m0 = mn0; m1 = mn1;
        float sum0 = 0.f, sum1 = 0.f;
        #pragma unroll
        for (int nt = 0; nt < 8; nt++) {
            s[nt][0] = __expf(s[nt][0] - mn0);
            s[nt][1] = __expf(s[nt][1] - mn0);
            s[nt][2] = __expf(s[nt][2] - mn1);
            s[nt][3] = __expf(s[nt][3] - mn1);
            sum0 += s[nt][0] + s[nt][1];
            sum1 += s[nt][2] + s[nt][3];
        }
        sum0 += __shfl_xor_sync(0xffffffffu, sum0, 1);
        sum0 += __shfl_xor_sync(0xffffffffu, sum0, 2);
        sum1 += __shfl_xor_sync(0xffffffffu, sum1, 1);
        sum1 += __shfl_xor_sync(0xffffffffu, sum1, 2);
        l0 = l0 * f0 + sum0;
        l1 = l1 * f1 + sum1;
        #pragma unroll
        for (int nt = 0; nt < 8; nt++) {
            O[nt][0] *= f0; O[nt][1] *= f0;
            O[nt][2] *= f1; O[nt][3] *= f1;
        }

        // ---- O += P @ V ----
        #pragma unroll
        for (int kc = 0; kc < 4; kc++) {
            uint32_t phi[4], plo[4];
            split2(s[2 * kc][0],     s[2 * kc][1],     phi[0], plo[0]);
            split2(s[2 * kc][2],     s[2 * kc][3],     phi[1], plo[1]);
            split2(s[2 * kc + 1][0], s[2 * kc + 1][1], phi[2], plo[2]);
            split2(s[2 * kc + 1][2], s[2 * kc + 1][3], phi[3], plo[3]);
            #pragma unroll
            for (int nt = 0; nt < 8; nt++) {
                int vr = kc * 16 + (lane & 15);
                uint32_t boff = (uint32_t)((vr * A_STR + nt * 8) * 2);
                uint32_t bhi[2], blo[2];
                ldsm_x2_trans(bhi, kvu + VHI_OFF * 2 + boff);
                ldsm_x2_trans(blo, kvu + VLO_OFF * 2 + boff);
                mma_bf16(O[nt], phi, bhi);
                mma_bf16(O[nt], phi, blo);
                mma_bf16(O[nt], plo, bhi);
            }
        }

        // ---- STS V(kt+1) into other buffer ----
        if (have_next) {
            #pragma unroll
            for (int i = 0; i < 4; i++) {
                uint32_t h0, l0r, h1, l1r;
                split2(vf[i].x, vf[i].y, h0, l0r);
                split2(vf[i].z, vf[i].w, h1, l1r);
                int off = lkey * A_STR + lc0 + i * 4;
                *(uint2*)(nxt + VHI_OFF + off) = make_uint2(h0, h1);
                *(uint2*)(nxt + VLO_OFF + off) = make_uint2(l0r, l1r);
            }
        }
        __syncthreads();
    }

    // ---- epilogue ----
    float inv0 = 1.0f / l0, inv1 = 1.0f / l1;
    #pragma unroll
    for (int nt = 0; nt < 8; nt++) {
        int c = h * HD + nt * 8 + (lane & 3) * 2;
        float2 o0, o1;
        o0.x = O[nt][0] * inv0; o0.y = O[nt][1] * inv0;
        o1.x = O[nt][2] * inv1; o1.y = O[nt][3] * inv1;
        *(float2*)(g_ctx + (size_t)(t0 + r0) * BD + b * D_MODEL + c) = o0;
        *(float2*)(g_ctx + (size_t)(t0 + r1) * BD + b * D_MODEL + c) = o1;
    }
}

// ---------------- launch ----------------
extern "C" void kernel_launch(void* const* d_in, const int* in_sizes, int n_in,
                              void* d_out, int out_size) {
    const float* query = (const float*)d_in[0];
    const float* key   = (const float*)d_in[1];
    const float* value = (const float*)d_in[2];
    const float* wq    = (const float*)d_in[3];
    const float* bq    = (const float*)d_in[4];
    const float* wk    = (const float*)d_in[5];
    const float* bk    = (const float*)d_in[6];
    const float* wv    = (const float*)d_in[7];
    const float* bv    = (const float*)d_in[8];
    const float* wo    = (const float*)d_in[9];
    const float* bo    = (const float*)d_in[10];
    const float* wte   = (const float*)d_in[11];
    const float* ct_w1 = (const float*)d_in[12];
    const float* ct_b1 = (const float*)d_in[13];
    const float* ct_w2 = (const float*)d_in[14];
    const float* ct_b2 = (const float*)d_in[15];
    const int*   lang  = (const int*)d_in[16];
    float* out = (float*)d_out;

    (void)in_sizes; (void)n_in; (void)out_size;

    prefix_h_kernel<<<dim3(100, BATCH), 256>>>(wte, ct_w1, ct_b1, lang);
    prefix_kv_kernel<<<dim3(256, BATCH), 256>>>(ct_w2, ct_b2, lang);

    float* dq; cudaGetSymbolAddress((void**)&dq, g_q);
    float* dk; cudaGetSymbolAddress((void**)&dk, g_k);
    float* dv; cudaGetSymbolAddress((void**)&dv, g_v);
    float* dctx; cudaGetSymbolAddress((void**)&dctx, g_ctx);

    cudaFuncSetAttribute(gemm_mma_kernel, cudaFuncAttributeMaxDynamicSharedMemorySize,
                         GEMM_SMEM_BYTES);
    dim3 ggrid(D_MODEL / BN, ROWS / BM);   // (8, 32)
    gemm_mma_kernel<<<ggrid, 256, GEMM_SMEM_BYTES>>>(query, wq, bq, dq, SCALING);
    gemm_mma_kernel<<<ggrid, 256, GEMM_SMEM_BYTES>>>(key,   wk, bk, dk, 1.0f);
    gemm_mma_kernel<<<ggrid, 256, GEMM_SMEM_BYTES>>>(value, wv, bv, dv, 1.0f);

    size_t att_smem = ATT_SMEM_HALVES * sizeof(__nv_bfloat16);   // 110592 B
    cudaFuncSetAttribute(attn_mma_kernel, cudaFuncAttributeMaxDynamicSharedMemorySize,
                         (int)att_smem);
    attn_mma_kernel<<<dim3(T_LEN / 128, NHEAD, BATCH), 256, att_smem>>>();

    gemm_mma_kernel<<<ggrid, 256, GEMM_SMEM_BYTES>>>(dctx, wo, bo, out, 1.0f);
}